// round 15
// baseline (speedup 1.0000x reference)
#include <cuda_runtime.h>
#include <cuda_fp16.h>
#include <math.h>

#define Nn 12288
#define Ff 256
#define Hh 64
#define Cc 16
#define MAXDEG 256
#define ALPHAc 0.3f
#define LN_EPS 1e-5f

#define GEMM_BLOCKS 384
#define CSR_BLOCKS  768          // warp w handles rows {w, Nn-1-w}, upper triangle only

// ---------------- scratch ----------------
__device__ int    g_colidx[Nn * MAXDEG];
__device__ int    g_deg[Nn];             // atomic insert counters == final degrees
__device__ float  g_dinv[Nn];
__device__ float  g_h0[Nn * Hh];
__device__ __half g_hsA[Nn * Hh];
__device__ __half g_hsB[Nn * Hh];
__device__ float  g_gm[Nn * Cc];
__device__ __half g_gs[Nn * Cc];
__device__ double g_acc[3];

// ---- zero counters + accumulators (before k_front on every replay) ----
__global__ void k_zero() {
    int i = blockIdx.x * blockDim.x + threadIdx.x;
    if (i < Nn) g_deg[i] = 0;
    if (i < 3) g_acc[i] = 0.0;
}

// ---- symmetric edge insert: (r,c) with c>r goes into both rows' lists ----
__device__ __forceinline__ void add_edge(int r, int c) {
    int p = atomicAdd(&g_deg[r], 1);
    g_colidx[r * MAXDEG + p] = c;
    int q = atomicAdd(&g_deg[c], 1);
    g_colidx[c * MAXDEG + q] = r;
}

__device__ __forceinline__ void edge4(uint4 v, int colb, int r) {
    if (v.x && (colb     > r)) add_edge(r, colb);
    if (v.y && (colb + 1 > r)) add_edge(r, colb + 1);
    if (v.z && (colb + 2 > r)) add_edge(r, colb + 2);
    if (v.w && (colb + 3 > r)) add_edge(r, colb + 3);
}

// ======= fused front: [0,384)=x@W_in GEMM ; [384,1152)=upper-triangle CSR =======
__global__ __launch_bounds__(256) void k_front(const float* __restrict__ adj,
                                               const float* __restrict__ x,
                                               const float* __restrict__ Win,
                                               const float* __restrict__ bin) {
    __shared__ float xs[32][33];
    __shared__ float Ws[32][64];
    int tid = threadIdx.x;

    if (blockIdx.x < GEMM_BLOCKS) {
        int tx = tid & 15, ty = tid >> 4;
        int row0 = blockIdx.x * 32;
        float acc[2][4];
        #pragma unroll
        for (int i = 0; i < 2; i++)
            #pragma unroll
            for (int jj = 0; jj < 4; jj++) acc[i][jj] = 0.f;

        const float* xBase = x + (size_t)row0 * Ff;
        int lr = tid >> 3, lk = (tid & 7) * 4;
        for (int kc = 0; kc < Ff; kc += 32) {
            float4 v = *(const float4*)(xBase + (size_t)lr * Ff + kc + lk);
            xs[lr][lk + 0] = v.x; xs[lr][lk + 1] = v.y;
            xs[lr][lk + 2] = v.z; xs[lr][lk + 3] = v.w;
            #pragma unroll
            for (int l = 0; l < 2; l++) {
                int q = tid + l * 256;
                int k = q >> 4, c4 = q & 15;
                *(float4*)&Ws[k][c4 * 4] =
                    ((const float4*)(Win + (size_t)(kc + k) * Hh))[c4];
            }
            __syncthreads();
            #pragma unroll
            for (int kk = 0; kk < 32; kk++) {
                float4 b = *(const float4*)&Ws[kk][tx * 4];
                float a0 = xs[ty * 2 + 0][kk];
                float a1 = xs[ty * 2 + 1][kk];
                acc[0][0] = fmaf(a0, b.x, acc[0][0]); acc[0][1] = fmaf(a0, b.y, acc[0][1]);
                acc[0][2] = fmaf(a0, b.z, acc[0][2]); acc[0][3] = fmaf(a0, b.w, acc[0][3]);
                acc[1][0] = fmaf(a1, b.x, acc[1][0]); acc[1][1] = fmaf(a1, b.y, acc[1][1]);
                acc[1][2] = fmaf(a1, b.z, acc[1][2]); acc[1][3] = fmaf(a1, b.w, acc[1][3]);
            }
            __syncthreads();
        }
        float4 bb = ((const float4*)bin)[tx];
        #pragma unroll
        for (int i = 0; i < 2; i++) {
            int row = row0 + ty * 2 + i;
            float4 v;
            v.x = acc[i][0] + bb.x; v.y = acc[i][1] + bb.y;
            v.z = acc[i][2] + bb.z; v.w = acc[i][3] + bb.w;
            ((float4*)g_h0)[row * 16 + tx] = v;
        }
    } else {
        int w = (blockIdx.x - GEMM_BLOCKS) * 8 + (tid >> 5);
        int lane = tid & 31;
        #pragma unroll 1
        for (int half = 0; half < 2; half++) {
            int r = half ? (Nn - 1 - w) : w;
            const uint4* arow = (const uint4*)(adj + (size_t)r * Nn);
            int sg = ((r + 1) >> 2) & ~127;     // 512-float aligned start group
            #pragma unroll 1
            for (int c0 = sg; c0 < Nn / 4; c0 += 128) {
                uint4 v0 = __ldcs(&arow[c0 +  0 + lane]);
                uint4 v1 = __ldcs(&arow[c0 + 32 + lane]);
                uint4 v2 = __ldcs(&arow[c0 + 64 + lane]);
                uint4 v3 = __ldcs(&arow[c0 + 96 + lane]);
                edge4(v0, (c0 +  0 + lane) * 4, r);
                edge4(v1, (c0 + 32 + lane) * 4, r);
                edge4(v2, (c0 + 64 + lane) * 4, r);
                edge4(v3, (c0 + 96 + lane) * 4, r);
            }
        }
    }
}

// ======= mid2: dinv + hsA = fp16(dinv*h0), fully coalesced elementwise =======
__global__ void k_mid2() {
    int idx = blockIdx.x * blockDim.x + threadIdx.x;   // [0, Nn*Hh)
    int row = idx >> 6;
    float du = rsqrtf((float)g_deg[row] + 1.0f);
    if ((idx & 63) == 0) g_dinv[row] = du;
    g_hsA[idx] = __float2half_rn(du * g_h0[idx]);
}

// ======= LN layers: warp = 1 row; 2 edge-groups of 16 threads split the gather =======
__global__ __launch_bounds__(256) void k_layer(const __half* __restrict__ hs_in,
                                               __half* __restrict__ hs_out,
                                               const float* __restrict__ Wc,
                                               const float* __restrict__ lng,
                                               const float* __restrict__ lnb,
                                               float beta) {
    __shared__ float sW[Hh * Hh];
    __shared__ float sHm[8][Hh + 4];
    for (int i = threadIdx.x; i < Hh * Hh / 4; i += 256)
        ((float4*)sW)[i] = ((const float4*)Wc)[i];
    __syncthreads();

    int r = threadIdx.x >> 5, lane = threadIdx.x & 31;
    int j = lane & 15, grp = lane >> 4;
    int row = blockIdx.x * 8 + r;
    float du = g_dinv[row];
    const uint2* hs2 = (const uint2*)hs_in;

    int deg = g_deg[row];
    const int* ci = g_colidx + row * MAXDEG;
    int dh = deg >> 1;
    int e  = grp ? dh : 0;
    int e1 = grp ? deg : dh;

    float ax, ay, az, aw;
    if (grp == 0) {
        uint2 s0 = __ldg(&hs2[row * 16 + j]);
        float2 f0 = __half22float2(*(__half2*)&s0.x);
        float2 f1 = __half22float2(*(__half2*)&s0.y);
        ax = f0.x; ay = f0.y; az = f1.x; aw = f1.y;
    } else {
        ax = 0.f; ay = 0.f; az = 0.f; aw = 0.f;
    }
    float bx = 0.f, by = 0.f, bz = 0.f, bw = 0.f;
    float cx = 0.f, cy = 0.f, cz = 0.f, cw = 0.f;
    float ex_ = 0.f, ey_ = 0.f, ez_ = 0.f, ew_ = 0.f;
    #pragma unroll 1
    for (; e + 4 <= e1; e += 4) {
        uint2 u0 = __ldg(&hs2[__ldg(&ci[e + 0]) * 16 + j]);
        uint2 u1 = __ldg(&hs2[__ldg(&ci[e + 1]) * 16 + j]);
        uint2 u2 = __ldg(&hs2[__ldg(&ci[e + 2]) * 16 + j]);
        uint2 u3 = __ldg(&hs2[__ldg(&ci[e + 3]) * 16 + j]);
        float2 g;
        g = __half22float2(*(__half2*)&u0.x); ax += g.x; ay += g.y;
        g = __half22float2(*(__half2*)&u0.y); az += g.x; aw += g.y;
        g = __half22float2(*(__half2*)&u1.x); bx += g.x; by += g.y;
        g = __half22float2(*(__half2*)&u1.y); bz += g.x; bw += g.y;
        g = __half22float2(*(__half2*)&u2.x); cx += g.x; cy += g.y;
        g = __half22float2(*(__half2*)&u2.y); cz += g.x; cw += g.y;
        g = __half22float2(*(__half2*)&u3.x); ex_ += g.x; ey_ += g.y;
        g = __half22float2(*(__half2*)&u3.y); ez_ += g.x; ew_ += g.y;
    }
    for (; e < e1; e++) {
        uint2 u0 = __ldg(&hs2[__ldg(&ci[e]) * 16 + j]);
        float2 g;
        g = __half22float2(*(__half2*)&u0.x); ax += g.x; ay += g.y;
        g = __half22float2(*(__half2*)&u0.y); az += g.x; aw += g.y;
    }
    ax += bx + cx + ex_;
    ay += by + cy + ey_;
    az += bz + cz + ez_;
    aw += bw + cw + ew_;
    ax += __shfl_xor_sync(0xffffffffu, ax, 16);
    ay += __shfl_xor_sync(0xffffffffu, ay, 16);
    az += __shfl_xor_sync(0xffffffffu, az, 16);
    aw += __shfl_xor_sync(0xffffffffu, aw, 16);

    float4 h0v = __ldg(&((const float4*)g_h0)[row * 16 + j]);
    float c1 = (1.f - ALPHAc) * du;
    float4 hm;
    hm.x = fmaf(c1, ax, ALPHAc * h0v.x);
    hm.y = fmaf(c1, ay, ALPHAc * h0v.y);
    hm.z = fmaf(c1, az, ALPHAc * h0v.z);
    hm.w = fmaf(c1, aw, ALPHAc * h0v.w);
    if (grp == 0) *(float4*)&sHm[r][4 * j] = hm;
    __syncwarp();

    float tx = 0.f, ty = 0.f;
    const float* hmrow = sHm[r];
    #pragma unroll
    for (int k = 0; k < Hh; k++) {
        float hk = hmrow[k];
        float2 w = *(const float2*)&sW[k * Hh + 2 * lane];
        tx = fmaf(hk, w.x, tx);
        ty = fmaf(hk, w.y, ty);
    }
    float hmx = hmrow[2 * lane], hmy = hmrow[2 * lane + 1];
    float vx = fmaf(beta, tx - hmx, hmx);
    float vy = fmaf(beta, ty - hmy, hmy);

    vx = fmaxf(vx, 0.f); vy = fmaxf(vy, 0.f);
    float s = vx + vy;
    #pragma unroll
    for (int d = 16; d; d >>= 1) s += __shfl_xor_sync(0xffffffffu, s, d);
    float mu = s * (1.f / 64.f);
    float dx = vx - mu, dy = vy - mu;
    float q = dx * dx + dy * dy;
    #pragma unroll
    for (int d = 16; d; d >>= 1) q += __shfl_xor_sync(0xffffffffu, q, d);
    float rstd = rsqrtf(q * (1.f / 64.f) + LN_EPS);
    float2 gg = ((const float2*)lng)[lane];
    float2 bb = ((const float2*)lnb)[lane];
    vx = fmaf(dx * rstd, gg.x, bb.x);
    vy = fmaf(dy * rstd, gg.y, bb.y);
    __half2 p = __floats2half2_rn(du * vx, du * vy);
    ((unsigned*)hs_out)[row * 32 + lane] = *(unsigned*)&p;
}

// ---- 16-thr/row gather for the final fused layer ----
__device__ __forceinline__ float4 gather_row16(const uint2* hs2, int row, int j) {
    float2 f0, f1;
    {
        uint2 s0 = __ldg(&hs2[row * 16 + j]);
        f0 = __half22float2(*(__half2*)&s0.x);
        f1 = __half22float2(*(__half2*)&s0.y);
    }
    float ax = f0.x, ay = f0.y, az = f1.x, aw = f1.y;
    float bx = 0.f, by = 0.f, bz = 0.f, bw = 0.f;
    float cx = 0.f, cy = 0.f, cz = 0.f, cw = 0.f;
    float ex_ = 0.f, ey_ = 0.f, ez_ = 0.f, ew_ = 0.f;
    int deg = g_deg[row];
    const int* ci = g_colidx + row * MAXDEG;
    int e = 0;
    #pragma unroll 1
    for (; e + 4 <= deg; e += 4) {
        uint2 u0 = __ldg(&hs2[__ldg(&ci[e + 0]) * 16 + j]);
        uint2 u1 = __ldg(&hs2[__ldg(&ci[e + 1]) * 16 + j]);
        uint2 u2 = __ldg(&hs2[__ldg(&ci[e + 2]) * 16 + j]);
        uint2 u3 = __ldg(&hs2[__ldg(&ci[e + 3]) * 16 + j]);
        float2 g;
        g = __half22float2(*(__half2*)&u0.x); ax += g.x; ay += g.y;
        g = __half22float2(*(__half2*)&u0.y); az += g.x; aw += g.y;
        g = __half22float2(*(__half2*)&u1.x); bx += g.x; by += g.y;
        g = __half22float2(*(__half2*)&u1.y); bz += g.x; bw += g.y;
        g = __half22float2(*(__half2*)&u2.x); cx += g.x; cy += g.y;
        g = __half22float2(*(__half2*)&u2.y); cz += g.x; cw += g.y;
        g = __half22float2(*(__half2*)&u3.x); ex_ += g.x; ey_ += g.y;
        g = __half22float2(*(__half2*)&u3.y); ez_ += g.x; ew_ += g.y;
    }
    for (; e < deg; e++) {
        uint2 u0 = __ldg(&hs2[__ldg(&ci[e]) * 16 + j]);
        float2 g;
        g = __half22float2(*(__half2*)&u0.x); ax += g.x; ay += g.y;
        g = __half22float2(*(__half2*)&u0.y); az += g.x; aw += g.y;
    }
    float4 o;
    o.x = ax + bx + cx + ex_;
    o.y = ay + by + cy + ey_;
    o.z = az + bz + cz + ez_;
    o.w = aw + bw + cw + ew_;
    return o;
}

// ======= final layer fused with output head (no rowsum atomics here anymore) =======
__global__ __launch_bounds__(256) void k_layer_last(const __half* __restrict__ hs_in,
                                                    const float* __restrict__ Wc,
                                                    const float* __restrict__ Wout,
                                                    const float* __restrict__ bout,
                                                    float beta,
                                                    float* __restrict__ dout) {
    __shared__ float sW[Hh * Hh];
    __shared__ float sWo[Hh * Cc];
    __shared__ float sHm[16][Hh + 4];
    for (int i = threadIdx.x; i < Hh * Hh / 4; i += 256)
        ((float4*)sW)[i] = ((const float4*)Wc)[i];
    if (threadIdx.x < Hh * Cc / 4)
        ((float4*)sWo)[threadIdx.x] = ((const float4*)Wout)[threadIdx.x];
    int r = threadIdx.x >> 4, j = threadIdx.x & 15;
    int row = blockIdx.x * 16 + r;
    float du = g_dinv[row];

    float4 a = gather_row16((const uint2*)hs_in, row, j);

    float4 h0v = ((const float4*)g_h0)[row * 16 + j];
    float c1 = (1.f - ALPHAc) * du;
    float4 hm;
    hm.x = fmaf(c1, a.x, ALPHAc * h0v.x);
    hm.y = fmaf(c1, a.y, ALPHAc * h0v.y);
    hm.z = fmaf(c1, a.z, ALPHAc * h0v.z);
    hm.w = fmaf(c1, a.w, ALPHAc * h0v.w);
    *(float4*)&sHm[r][4 * j] = hm;
    __syncthreads();

    float4 t = make_float4(0.f, 0.f, 0.f, 0.f);
    const float* hmrow = sHm[r];
    #pragma unroll
    for (int k = 0; k < Hh; k++) {
        float hk = hmrow[k];
        float4 w = *(const float4*)&sW[k * Hh + 4 * j];
        t.x = fmaf(hk, w.x, t.x);
        t.y = fmaf(hk, w.y, t.y);
        t.z = fmaf(hk, w.z, t.z);
        t.w = fmaf(hk, w.w, t.w);
    }
    float4 v;
    v.x = fmaf(beta, t.x - hm.x, hm.x);
    v.y = fmaf(beta, t.y - hm.y, hm.y);
    v.z = fmaf(beta, t.z - hm.z, hm.z);
    v.w = fmaf(beta, t.w - hm.w, hm.w);

    __syncwarp();
    *(float4*)&sHm[r][4 * j] = v;
    __syncwarp();

    const float* vr = sHm[r];
    float o = bout[j];
    #pragma unroll
    for (int k = 0; k < Hh; k++) o = fmaf(vr[k], sWo[k * Cc + j], o);
    dout[row * Cc + j] = o;
    float m = o;
    #pragma unroll
    for (int d = 1; d < 16; d <<= 1) m = fmaxf(m, __shfl_xor_sync(0xffffffffu, m, d));
    float ex = expf(o - m);
    float se = ex;
    #pragma unroll
    for (int d = 1; d < 16; d <<= 1) se += __shfl_xor_sync(0xffffffffu, se, d);
    dout[Nn * Cc + row * Cc + j] = o - m - logf(se);

    float gv = fmaxf(o, 0.f) * rsqrtf((float)g_deg[row] + 2.0f);
    g_gm[row * Cc + j] = gv;
    g_gs[row * Cc + j] = __float2half_rn(du * gv);
}

// ---- Dirichlet tail: term1 (rowsum*s), term2 ((W@g).g), Wsum — all per-row here ----
__global__ void k_wg() {
    int row = blockIdx.x * 32 + (threadIdx.x >> 3);
    int q = threadIdx.x & 7;
    const unsigned* gs2 = (const unsigned*)g_gs;
    float du = g_dinv[row];
    float ax, ay;
    {
        float2 f = __half22float2(*(const __half2*)&gs2[row * 8 + q]);
        ax = f.x; ay = f.y;
    }
    float bx = 0.f, by = 0.f, cx = 0.f, cy = 0.f, dxx = 0.f, dyy = 0.f;
    int deg = g_deg[row];
    const int* ci = g_colidx + row * MAXDEG;
    int e = 0;
    #pragma unroll 1
    for (; e + 4 <= deg; e += 4) {
        unsigned u0 = __ldg(&gs2[__ldg(&ci[e])     * 8 + q]);
        unsigned u1 = __ldg(&gs2[__ldg(&ci[e + 1]) * 8 + q]);
        unsigned u2 = __ldg(&gs2[__ldg(&ci[e + 2]) * 8 + q]);
        unsigned u3 = __ldg(&gs2[__ldg(&ci[e + 3]) * 8 + q]);
        float2 f;
        f = __half22float2(*(__half2*)&u0); ax += f.x; ay += f.y;
        f = __half22float2(*(__half2*)&u1); bx += f.x; by += f.y;
        f = __half22float2(*(__half2*)&u2); cx += f.x; cy += f.y;
        f = __half22float2(*(__half2*)&u3); dxx += f.x; dyy += f.y;
    }
    for (; e < deg; e++) {
        float2 f = __half22float2(*(const __half2*)&gs2[__ldg(&ci[e]) * 8 + q]);
        ax += f.x; ay += f.y;
    }
    ax += bx + cx + dxx; ay += by + cy + dyy;

    // neighbor dinv sum for rowsum (strided across the 8 threads)
    float sd = 0.f;
    #pragma unroll 1
    for (int e2 = q; e2 < deg; e2 += 8) sd += __ldg(&g_dinv[__ldg(&ci[e2])]);

    float2 gu = ((const float2*)g_gm)[row * 8 + q];
    float dot = ax * gu.x + ay * gu.y;
    float sq  = gu.x * gu.x + gu.y * gu.y;
    #pragma unroll
    for (int d = 1; d < 8; d <<= 1) {
        dot += __shfl_xor_sync(0xffffffffu, dot, d);
        sq  += __shfl_xor_sync(0xffffffffu, sq,  d);
        sd  += __shfl_xor_sync(0xffffffffu, sd,  d);
    }
    if (q == 0) {
        float rowsum = du * (du + sd);
        atomicAdd(&g_acc[0], (double)(rowsum * sq));
        atomicAdd(&g_acc[1], (double)(du * dot));
        atomicAdd(&g_acc[2], (double)rowsum);
    }
}

__global__ void k_fin(float* __restrict__ dout) {
    dout[2 * Nn * Cc] = (float)((g_acc[0] - g_acc[1]) / g_acc[2]);
}

// ---------------- launch ----------------
extern "C" void kernel_launch(void* const* d_in, const int* in_sizes, int n_in,
                              void* d_out, int out_size) {
    const float* x    = (const float*)d_in[0];
    const float* adj  = (const float*)d_in[1];
    const float* Win  = (const float*)d_in[2];
    const float* bin  = (const float*)d_in[3];
    const float* Wcv  = (const float*)d_in[4];
    const float* lng  = (const float*)d_in[5];
    const float* lnb  = (const float*)d_in[6];
    const float* Wout = (const float*)d_in[7];
    const float* bout = (const float*)d_in[8];
    float* out = (float*)d_out;

    k_zero<<<Nn / 1024, 1024>>>();
    k_front<<<GEMM_BLOCKS + CSR_BLOCKS, 256>>>(adj, x, Win, bin);
    k_mid2<<<Nn * Hh / 256, 256>>>();

    void* hsA_p = nullptr; void* hsB_p = nullptr;
    cudaGetSymbolAddress(&hsA_p, g_hsA);
    cudaGetSymbolAddress(&hsB_p, g_hsB);
    __half* hsA = (__half*)hsA_p;
    __half* hsB = (__half*)hsB_p;

    const float betas[4] = {0.26236426446749106f, 0.13976194237515863f,
                            0.09531017980432486f, 0.07232066157962608f};
    k_layer<<<Nn / 8, 256>>>(hsA, hsB, Wcv + 0 * Hh * Hh, lng + 0 * Hh, lnb + 0 * Hh, betas[0]);
    k_layer<<<Nn / 8, 256>>>(hsB, hsA, Wcv + 1 * Hh * Hh, lng + 1 * Hh, lnb + 1 * Hh, betas[1]);
    k_layer<<<Nn / 8, 256>>>(hsA, hsB, Wcv + 2 * Hh * Hh, lng + 2 * Hh, lnb + 2 * Hh, betas[2]);
    k_layer_last<<<Nn / 16, 256>>>(hsB, Wcv + 3 * Hh * Hh, Wout, bout, betas[3], out);

    k_wg<<<Nn / 32, 256>>>();
    k_fin<<<1, 1>>>(out);
}

// round 16
// speedup vs baseline: 1.0083x; 1.0083x over previous
#include <cuda_runtime.h>
#include <cuda_fp16.h>
#include <math.h>

#define Nn 12288
#define Ff 256
#define Hh 64
#define Cc 16
#define MAXDEG 256
#define ALPHAc 0.3f
#define LN_EPS 1e-5f

#define GEMM_BLOCKS 384
#define CSR_BLOCKS  768          // warp w handles rows {w, Nn-1-w}, upper triangle only

// ---------------- scratch ----------------
__device__ int    g_colidx[Nn * MAXDEG];
__device__ int    g_deg[Nn];             // atomic insert counters == final degrees
__device__ float  g_dinv[Nn];
__device__ float  g_h0[Nn * Hh];
__device__ __half g_hsA[Nn * Hh];
__device__ __half g_hsB[Nn * Hh];
__device__ float  g_gm[Nn * Cc];
__device__ __half g_gs[Nn * Cc];
__device__ double g_acc[3];

// ---- zero counters + accumulators (before k_front on every replay) ----
__global__ void k_zero() {
    int i = blockIdx.x * blockDim.x + threadIdx.x;
    if (i < Nn) g_deg[i] = 0;
    if (i < 3) g_acc[i] = 0.0;
}

// ---- symmetric edge insert: (r,c) with c>r goes into both rows' lists ----
__device__ __forceinline__ void add_edge(int r, int c) {
    int p = atomicAdd(&g_deg[r], 1);
    g_colidx[r * MAXDEG + p] = c;
    int q = atomicAdd(&g_deg[c], 1);
    g_colidx[c * MAXDEG + q] = r;
}

__device__ __forceinline__ void edge4(uint4 v, int colb, int r) {
    if (v.x && (colb     > r)) add_edge(r, colb);
    if (v.y && (colb + 1 > r)) add_edge(r, colb + 1);
    if (v.z && (colb + 2 > r)) add_edge(r, colb + 2);
    if (v.w && (colb + 3 > r)) add_edge(r, colb + 3);
}

// ======= fused front: [0,384)=x@W_in GEMM ; [384,1152)=upper-triangle CSR =======
__global__ __launch_bounds__(256) void k_front(const float* __restrict__ adj,
                                               const float* __restrict__ x,
                                               const float* __restrict__ Win,
                                               const float* __restrict__ bin) {
    __shared__ float xs[32][33];
    __shared__ float Ws[32][64];
    int tid = threadIdx.x;

    if (blockIdx.x < GEMM_BLOCKS) {
        int tx = tid & 15, ty = tid >> 4;
        int row0 = blockIdx.x * 32;
        float acc[2][4];
        #pragma unroll
        for (int i = 0; i < 2; i++)
            #pragma unroll
            for (int jj = 0; jj < 4; jj++) acc[i][jj] = 0.f;

        const float* xBase = x + (size_t)row0 * Ff;
        int lr = tid >> 3, lk = (tid & 7) * 4;
        for (int kc = 0; kc < Ff; kc += 32) {
            float4 v = *(const float4*)(xBase + (size_t)lr * Ff + kc + lk);
            xs[lr][lk + 0] = v.x; xs[lr][lk + 1] = v.y;
            xs[lr][lk + 2] = v.z; xs[lr][lk + 3] = v.w;
            #pragma unroll
            for (int l = 0; l < 2; l++) {
                int q = tid + l * 256;
                int k = q >> 4, c4 = q & 15;
                *(float4*)&Ws[k][c4 * 4] =
                    ((const float4*)(Win + (size_t)(kc + k) * Hh))[c4];
            }
            __syncthreads();
            #pragma unroll
            for (int kk = 0; kk < 32; kk++) {
                float4 b = *(const float4*)&Ws[kk][tx * 4];
                float a0 = xs[ty * 2 + 0][kk];
                float a1 = xs[ty * 2 + 1][kk];
                acc[0][0] = fmaf(a0, b.x, acc[0][0]); acc[0][1] = fmaf(a0, b.y, acc[0][1]);
                acc[0][2] = fmaf(a0, b.z, acc[0][2]); acc[0][3] = fmaf(a0, b.w, acc[0][3]);
                acc[1][0] = fmaf(a1, b.x, acc[1][0]); acc[1][1] = fmaf(a1, b.y, acc[1][1]);
                acc[1][2] = fmaf(a1, b.z, acc[1][2]); acc[1][3] = fmaf(a1, b.w, acc[1][3]);
            }
            __syncthreads();
        }
        float4 bb = ((const float4*)bin)[tx];
        #pragma unroll
        for (int i = 0; i < 2; i++) {
            int row = row0 + ty * 2 + i;
            float4 v;
            v.x = acc[i][0] + bb.x; v.y = acc[i][1] + bb.y;
            v.z = acc[i][2] + bb.z; v.w = acc[i][3] + bb.w;
            ((float4*)g_h0)[row * 16 + tx] = v;
        }
    } else {
        int w = (blockIdx.x - GEMM_BLOCKS) * 8 + (tid >> 5);
        int lane = tid & 31;
        #pragma unroll 1
        for (int half = 0; half < 2; half++) {
            int r = half ? (Nn - 1 - w) : w;
            const uint4* arow = (const uint4*)(adj + (size_t)r * Nn);
            int sg = ((r + 1) >> 2) & ~127;     // 512-float aligned start group
            #pragma unroll 1
            for (int c0 = sg; c0 < Nn / 4; c0 += 128) {
                uint4 v0 = __ldcs(&arow[c0 +  0 + lane]);
                uint4 v1 = __ldcs(&arow[c0 + 32 + lane]);
                uint4 v2 = __ldcs(&arow[c0 + 64 + lane]);
                uint4 v3 = __ldcs(&arow[c0 + 96 + lane]);
                edge4(v0, (c0 +  0 + lane) * 4, r);
                edge4(v1, (c0 + 32 + lane) * 4, r);
                edge4(v2, (c0 + 64 + lane) * 4, r);
                edge4(v3, (c0 + 96 + lane) * 4, r);
            }
        }
    }
}

// ======= mid2: dinv + hsA = fp16(dinv*h0), fully coalesced elementwise =======
__global__ void k_mid2() {
    int idx = blockIdx.x * blockDim.x + threadIdx.x;   // [0, Nn*Hh)
    int row = idx >> 6;
    float du = rsqrtf((float)g_deg[row] + 1.0f);
    if ((idx & 63) == 0) g_dinv[row] = du;
    g_hsA[idx] = __float2half_rn(du * g_h0[idx]);
}

// ======= LN layers: warp = 1 row; 2 edge-groups of 16 threads split the gather =======
__global__ __launch_bounds__(256) void k_layer(const __half* __restrict__ hs_in,
                                               __half* __restrict__ hs_out,
                                               const float* __restrict__ Wc,
                                               const float* __restrict__ lng,
                                               const float* __restrict__ lnb,
                                               float beta) {
    __shared__ float sW[Hh * Hh];
    __shared__ float sHm[8][Hh + 4];
    for (int i = threadIdx.x; i < Hh * Hh / 4; i += 256)
        ((float4*)sW)[i] = ((const float4*)Wc)[i];
    __syncthreads();

    int r = threadIdx.x >> 5, lane = threadIdx.x & 31;
    int j = lane & 15, grp = lane >> 4;
    int row = blockIdx.x * 8 + r;
    float du = g_dinv[row];
    const uint2* hs2 = (const uint2*)hs_in;

    int deg = g_deg[row];
    const int* ci = g_colidx + row * MAXDEG;
    int dh = deg >> 1;
    int e  = grp ? dh : 0;
    int e1 = grp ? deg : dh;

    float ax, ay, az, aw;
    if (grp == 0) {
        uint2 s0 = __ldg(&hs2[row * 16 + j]);
        float2 f0 = __half22float2(*(__half2*)&s0.x);
        float2 f1 = __half22float2(*(__half2*)&s0.y);
        ax = f0.x; ay = f0.y; az = f1.x; aw = f1.y;
    } else {
        ax = 0.f; ay = 0.f; az = 0.f; aw = 0.f;
    }
    float bx = 0.f, by = 0.f, bz = 0.f, bw = 0.f;
    float cx = 0.f, cy = 0.f, cz = 0.f, cw = 0.f;
    float ex_ = 0.f, ey_ = 0.f, ez_ = 0.f, ew_ = 0.f;
    #pragma unroll 1
    for (; e + 4 <= e1; e += 4) {
        uint2 u0 = __ldg(&hs2[__ldg(&ci[e + 0]) * 16 + j]);
        uint2 u1 = __ldg(&hs2[__ldg(&ci[e + 1]) * 16 + j]);
        uint2 u2 = __ldg(&hs2[__ldg(&ci[e + 2]) * 16 + j]);
        uint2 u3 = __ldg(&hs2[__ldg(&ci[e + 3]) * 16 + j]);
        float2 g;
        g = __half22float2(*(__half2*)&u0.x); ax += g.x; ay += g.y;
        g = __half22float2(*(__half2*)&u0.y); az += g.x; aw += g.y;
        g = __half22float2(*(__half2*)&u1.x); bx += g.x; by += g.y;
        g = __half22float2(*(__half2*)&u1.y); bz += g.x; bw += g.y;
        g = __half22float2(*(__half2*)&u2.x); cx += g.x; cy += g.y;
        g = __half22float2(*(__half2*)&u2.y); cz += g.x; cw += g.y;
        g = __half22float2(*(__half2*)&u3.x); ex_ += g.x; ey_ += g.y;
        g = __half22float2(*(__half2*)&u3.y); ez_ += g.x; ew_ += g.y;
    }
    for (; e < e1; e++) {
        uint2 u0 = __ldg(&hs2[__ldg(&ci[e]) * 16 + j]);
        float2 g;
        g = __half22float2(*(__half2*)&u0.x); ax += g.x; ay += g.y;
        g = __half22float2(*(__half2*)&u0.y); az += g.x; aw += g.y;
    }
    ax += bx + cx + ex_;
    ay += by + cy + ey_;
    az += bz + cz + ez_;
    aw += bw + cw + ew_;
    ax += __shfl_xor_sync(0xffffffffu, ax, 16);
    ay += __shfl_xor_sync(0xffffffffu, ay, 16);
    az += __shfl_xor_sync(0xffffffffu, az, 16);
    aw += __shfl_xor_sync(0xffffffffu, aw, 16);

    float4 h0v = __ldg(&((const float4*)g_h0)[row * 16 + j]);
    float c1 = (1.f - ALPHAc) * du;
    float4 hm;
    hm.x = fmaf(c1, ax, ALPHAc * h0v.x);
    hm.y = fmaf(c1, ay, ALPHAc * h0v.y);
    hm.z = fmaf(c1, az, ALPHAc * h0v.z);
    hm.w = fmaf(c1, aw, ALPHAc * h0v.w);
    if (grp == 0) *(float4*)&sHm[r][4 * j] = hm;
    __syncwarp();

    float tx = 0.f, ty = 0.f;
    const float* hmrow = sHm[r];
    #pragma unroll
    for (int k = 0; k < Hh; k++) {
        float hk = hmrow[k];
        float2 w = *(const float2*)&sW[k * Hh + 2 * lane];
        tx = fmaf(hk, w.x, tx);
        ty = fmaf(hk, w.y, ty);
    }
    float hmx = hmrow[2 * lane], hmy = hmrow[2 * lane + 1];
    float vx = fmaf(beta, tx - hmx, hmx);
    float vy = fmaf(beta, ty - hmy, hmy);

    vx = fmaxf(vx, 0.f); vy = fmaxf(vy, 0.f);
    float s = vx + vy;
    #pragma unroll
    for (int d = 16; d; d >>= 1) s += __shfl_xor_sync(0xffffffffu, s, d);
    float mu = s * (1.f / 64.f);
    float dx = vx - mu, dy = vy - mu;
    float q = dx * dx + dy * dy;
    #pragma unroll
    for (int d = 16; d; d >>= 1) q += __shfl_xor_sync(0xffffffffu, q, d);
    float rstd = rsqrtf(q * (1.f / 64.f) + LN_EPS);
    float2 gg = ((const float2*)lng)[lane];
    float2 bb = ((const float2*)lnb)[lane];
    vx = fmaf(dx * rstd, gg.x, bb.x);
    vy = fmaf(dy * rstd, gg.y, bb.y);
    __half2 p = __floats2half2_rn(du * vx, du * vy);
    ((unsigned*)hs_out)[row * 32 + lane] = *(unsigned*)&p;
}

// ---- 16-thr/row gather for the final fused layer ----
__device__ __forceinline__ float4 gather_row16(const uint2* hs2, int row, int j) {
    float2 f0, f1;
    {
        uint2 s0 = __ldg(&hs2[row * 16 + j]);
        f0 = __half22float2(*(__half2*)&s0.x);
        f1 = __half22float2(*(__half2*)&s0.y);
    }
    float ax = f0.x, ay = f0.y, az = f1.x, aw = f1.y;
    float bx = 0.f, by = 0.f, bz = 0.f, bw = 0.f;
    float cx = 0.f, cy = 0.f, cz = 0.f, cw = 0.f;
    float ex_ = 0.f, ey_ = 0.f, ez_ = 0.f, ew_ = 0.f;
    int deg = g_deg[row];
    const int* ci = g_colidx + row * MAXDEG;
    int e = 0;
    #pragma unroll 1
    for (; e + 4 <= deg; e += 4) {
        uint2 u0 = __ldg(&hs2[__ldg(&ci[e + 0]) * 16 + j]);
        uint2 u1 = __ldg(&hs2[__ldg(&ci[e + 1]) * 16 + j]);
        uint2 u2 = __ldg(&hs2[__ldg(&ci[e + 2]) * 16 + j]);
        uint2 u3 = __ldg(&hs2[__ldg(&ci[e + 3]) * 16 + j]);
        float2 g;
        g = __half22float2(*(__half2*)&u0.x); ax += g.x; ay += g.y;
        g = __half22float2(*(__half2*)&u0.y); az += g.x; aw += g.y;
        g = __half22float2(*(__half2*)&u1.x); bx += g.x; by += g.y;
        g = __half22float2(*(__half2*)&u1.y); bz += g.x; bw += g.y;
        g = __half22float2(*(__half2*)&u2.x); cx += g.x; cy += g.y;
        g = __half22float2(*(__half2*)&u2.y); cz += g.x; cw += g.y;
        g = __half22float2(*(__half2*)&u3.x); ex_ += g.x; ey_ += g.y;
        g = __half22float2(*(__half2*)&u3.y); ez_ += g.x; ew_ += g.y;
    }
    for (; e < deg; e++) {
        uint2 u0 = __ldg(&hs2[__ldg(&ci[e]) * 16 + j]);
        float2 g;
        g = __half22float2(*(__half2*)&u0.x); ax += g.x; ay += g.y;
        g = __half22float2(*(__half2*)&u0.y); az += g.x; aw += g.y;
    }
    float4 o;
    o.x = ax + bx + cx + ex_;
    o.y = ay + by + cy + ey_;
    o.z = az + bz + cz + ez_;
    o.w = aw + bw + cw + ew_;
    return o;
}

// ======= final layer fused with output head =======
__global__ __launch_bounds__(256) void k_layer_last(const __half* __restrict__ hs_in,
                                                    const float* __restrict__ Wc,
                                                    const float* __restrict__ Wout,
                                                    const float* __restrict__ bout,
                                                    float beta,
                                                    float* __restrict__ dout) {
    __shared__ float sW[Hh * Hh];
    __shared__ float sWo[Hh * Cc];
    __shared__ float sHm[16][Hh + 4];
    for (int i = threadIdx.x; i < Hh * Hh / 4; i += 256)
        ((float4*)sW)[i] = ((const float4*)Wc)[i];
    if (threadIdx.x < Hh * Cc / 4)
        ((float4*)sWo)[threadIdx.x] = ((const float4*)Wout)[threadIdx.x];
    int r = threadIdx.x >> 4, j = threadIdx.x & 15;
    int row = blockIdx.x * 16 + r;
    float du = g_dinv[row];

    float4 a = gather_row16((const uint2*)hs_in, row, j);

    float4 h0v = ((const float4*)g_h0)[row * 16 + j];
    float c1 = (1.f - ALPHAc) * du;
    float4 hm;
    hm.x = fmaf(c1, a.x, ALPHAc * h0v.x);
    hm.y = fmaf(c1, a.y, ALPHAc * h0v.y);
    hm.z = fmaf(c1, a.z, ALPHAc * h0v.z);
    hm.w = fmaf(c1, a.w, ALPHAc * h0v.w);
    *(float4*)&sHm[r][4 * j] = hm;
    __syncthreads();

    float4 t = make_float4(0.f, 0.f, 0.f, 0.f);
    const float* hmrow = sHm[r];
    #pragma unroll
    for (int k = 0; k < Hh; k++) {
        float hk = hmrow[k];
        float4 w = *(const float4*)&sW[k * Hh + 4 * j];
        t.x = fmaf(hk, w.x, t.x);
        t.y = fmaf(hk, w.y, t.y);
        t.z = fmaf(hk, w.z, t.z);
        t.w = fmaf(hk, w.w, t.w);
    }
    float4 v;
    v.x = fmaf(beta, t.x - hm.x, hm.x);
    v.y = fmaf(beta, t.y - hm.y, hm.y);
    v.z = fmaf(beta, t.z - hm.z, hm.z);
    v.w = fmaf(beta, t.w - hm.w, hm.w);

    __syncwarp();
    *(float4*)&sHm[r][4 * j] = v;
    __syncwarp();

    const float* vr = sHm[r];
    float o = bout[j];
    #pragma unroll
    for (int k = 0; k < Hh; k++) o = fmaf(vr[k], sWo[k * Cc + j], o);
    dout[row * Cc + j] = o;
    float m = o;
    #pragma unroll
    for (int d = 1; d < 16; d <<= 1) m = fmaxf(m, __shfl_xor_sync(0xffffffffu, m, d));
    float ex = expf(o - m);
    float se = ex;
    #pragma unroll
    for (int d = 1; d < 16; d <<= 1) se += __shfl_xor_sync(0xffffffffu, se, d);
    dout[Nn * Cc + row * Cc + j] = o - m - logf(se);

    float gv = fmaxf(o, 0.f) * rsqrtf((float)g_deg[row] + 2.0f);
    g_gm[row * Cc + j] = gv;
    g_gs[row * Cc + j] = __float2half_rn(du * gv);
}

// ---- Dirichlet tail: term1, term2, Wsum; dinv loads folded into the MLP-4 loop ----
__global__ void k_wg() {
    int row = blockIdx.x * 32 + (threadIdx.x >> 3);
    int q = threadIdx.x & 7;
    const unsigned* gs2 = (const unsigned*)g_gs;
    float du = g_dinv[row];
    float ax, ay;
    {
        float2 f = __half22float2(*(const __half2*)&gs2[row * 8 + q]);
        ax = f.x; ay = f.y;
    }
    float bx = 0.f, by = 0.f, cx = 0.f, cy = 0.f, dxx = 0.f, dyy = 0.f;
    float sd = 0.f;
    int deg = g_deg[row];
    const int* ci = g_colidx + row * MAXDEG;
    int e = 0;
    #pragma unroll 1
    for (; e + 4 <= deg; e += 4) {
        int i0 = __ldg(&ci[e]);
        int i1 = __ldg(&ci[e + 1]);
        int i2 = __ldg(&ci[e + 2]);
        int i3 = __ldg(&ci[e + 3]);
        unsigned u0 = __ldg(&gs2[i0 * 8 + q]);
        unsigned u1 = __ldg(&gs2[i1 * 8 + q]);
        unsigned u2 = __ldg(&gs2[i2 * 8 + q]);
        unsigned u3 = __ldg(&gs2[i3 * 8 + q]);
        if (q < 4) {   // threads 0-3 each take one dinv load per quad (full MLP)
            int isel = (q == 0) ? i0 : (q == 1) ? i1 : (q == 2) ? i2 : i3;
            sd += __ldg(&g_dinv[isel]);
        }
        float2 f;
        f = __half22float2(*(__half2*)&u0); ax += f.x; ay += f.y;
        f = __half22float2(*(__half2*)&u1); bx += f.x; by += f.y;
        f = __half22float2(*(__half2*)&u2); cx += f.x; cy += f.y;
        f = __half22float2(*(__half2*)&u3); dxx += f.x; dyy += f.y;
    }
    for (; e < deg; e++) {
        int i0 = __ldg(&ci[e]);
        float2 f = __half22float2(*(const __half2*)&gs2[i0 * 8 + q]);
        ax += f.x; ay += f.y;
        if (q == 0) sd += __ldg(&g_dinv[i0]);
    }
    ax += bx + cx + dxx; ay += by + cy + dyy;

    float2 gu = ((const float2*)g_gm)[row * 8 + q];
    float dot = ax * gu.x + ay * gu.y;
    float sq  = gu.x * gu.x + gu.y * gu.y;
    #pragma unroll
    for (int d = 1; d < 8; d <<= 1) {
        dot += __shfl_xor_sync(0xffffffffu, dot, d);
        sq  += __shfl_xor_sync(0xffffffffu, sq,  d);
        sd  += __shfl_xor_sync(0xffffffffu, sd,  d);
    }
    if (q == 0) {
        float rowsum = du * (du + sd);
        atomicAdd(&g_acc[0], (double)(rowsum * sq));
        atomicAdd(&g_acc[1], (double)(du * dot));
        atomicAdd(&g_acc[2], (double)rowsum);
    }
}

__global__ void k_fin(float* __restrict__ dout) {
    dout[2 * Nn * Cc] = (float)((g_acc[0] - g_acc[1]) / g_acc[2]);
}

// ---------------- launch ----------------
extern "C" void kernel_launch(void* const* d_in, const int* in_sizes, int n_in,
                              void* d_out, int out_size) {
    const float* x    = (const float*)d_in[0];
    const float* adj  = (const float*)d_in[1];
    const float* Win  = (const float*)d_in[2];
    const float* bin  = (const float*)d_in[3];
    const float* Wcv  = (const float*)d_in[4];
    const float* lng  = (const float*)d_in[5];
    const float* lnb  = (const float*)d_in[6];
    const float* Wout = (const float*)d_in[7];
    const float* bout = (const float*)d_in[8];
    float* out = (float*)d_out;

    k_zero<<<Nn / 1024, 1024>>>();
    k_front<<<GEMM_BLOCKS + CSR_BLOCKS, 256>>>(adj, x, Win, bin);
    k_mid2<<<Nn * Hh / 256, 256>>>();

    void* hsA_p = nullptr; void* hsB_p = nullptr;
    cudaGetSymbolAddress(&hsA_p, g_hsA);
    cudaGetSymbolAddress(&hsB_p, g_hsB);
    __half* hsA = (__half*)hsA_p;
    __half* hsB = (__half*)hsB_p;

    const float betas[4] = {0.26236426446749106f, 0.13976194237515863f,
                            0.09531017980432486f, 0.07232066157962608f};
    k_layer<<<Nn / 8, 256>>>(hsA, hsB, Wcv + 0 * Hh * Hh, lng + 0 * Hh, lnb + 0 * Hh, betas[0]);
    k_layer<<<Nn / 8, 256>>>(hsB, hsA, Wcv + 1 * Hh * Hh, lng + 1 * Hh, lnb + 1 * Hh, betas[1]);
    k_layer<<<Nn / 8, 256>>>(hsA, hsB, Wcv + 2 * Hh * Hh, lng + 2 * Hh, lnb + 2 * Hh, betas[2]);
    k_layer_last<<<Nn / 16, 256>>>(hsB, Wcv + 3 * Hh * Hh, Wout, bout, betas[3], out);

    k_wg<<<Nn / 32, 256>>>();
    k_fin<<<1, 1>>>(out);
}